// round 1
// baseline (speedup 1.0000x reference)
#include <cuda_runtime.h>

#define H 1024
#define V 50257

// ---------------- scratch (no allocation allowed) ----------------
__device__ float g_xbuf[3][H];        // [0]=embed out, [1]=layer0 out, [2]=layer1 out
__device__ float g_logits[V + 16];
__device__ float g_lse;

// ---------------- kernel 1: embedding + relu ----------------
__global__ void embed_relu_kernel(const long long* __restrict__ tok,
                                  const float* __restrict__ emb) {
    int i = blockIdx.x * blockDim.x + threadIdx.x;
    long long t = tok[0];
    float v = emb[t * (long long)H + i];
    g_xbuf[0][i] = v > 0.0f ? v : 0.0f;
}

__device__ __forceinline__ float dot4(float4 a, float4 b) {
    return a.x * b.x + a.y * b.y + a.z * b.z + a.w * b.w;
}

// ---------------- kernel 2: one GRU layer ----------------
// grid = H blocks, block = 256 threads. Block j computes output element j.
// Reads 6 weight rows (24 KB) fully coalesced as float4; x/h staged in SMEM.
__global__ void __launch_bounds__(256) gru_layer_kernel(
    int layer,
    const float* __restrict__ hidden,   // d_in[1], (L,1,H)
    const float* __restrict__ Wih,      // d_in[3] + layer*3H*H
    const float* __restrict__ Whh,      // d_in[4] + layer*3H*H
    const float* __restrict__ bih,      // d_in[5] + layer*3H
    const float* __restrict__ bhh,      // d_in[6] + layer*3H
    float* __restrict__ d_out)          // hidden_new goes to d_out[V + layer*H]
{
    __shared__ float4 sx[H / 4];
    __shared__ float4 sh[H / 4];
    __shared__ float sred[8][6];

    const float* x_in = g_xbuf[layer];          // layer0 reads embed, layer1 reads layer0 out
    const float* h_in = hidden + layer * H;

    int t = threadIdx.x;
    sx[t] = ((const float4*)x_in)[t];
    sh[t] = ((const float4*)h_in)[t];
    __syncthreads();

    int j = blockIdx.x;
    const float4* wr = (const float4*)(Wih + (size_t)j * H);
    const float4* wz = (const float4*)(Wih + (size_t)(H + j) * H);
    const float4* wn = (const float4*)(Wih + (size_t)(2 * H + j) * H);
    const float4* ur = (const float4*)(Whh + (size_t)j * H);
    const float4* uz = (const float4*)(Whh + (size_t)(H + j) * H);
    const float4* un = (const float4*)(Whh + (size_t)(2 * H + j) * H);

    float4 xv = sx[t];
    float4 hv = sh[t];
    float a0 = dot4(wr[t], xv);
    float a1 = dot4(wz[t], xv);
    float a2 = dot4(wn[t], xv);
    float a3 = dot4(ur[t], hv);
    float a4 = dot4(uz[t], hv);
    float a5 = dot4(un[t], hv);

    #pragma unroll
    for (int off = 16; off > 0; off >>= 1) {
        a0 += __shfl_down_sync(0xffffffffu, a0, off);
        a1 += __shfl_down_sync(0xffffffffu, a1, off);
        a2 += __shfl_down_sync(0xffffffffu, a2, off);
        a3 += __shfl_down_sync(0xffffffffu, a3, off);
        a4 += __shfl_down_sync(0xffffffffu, a4, off);
        a5 += __shfl_down_sync(0xffffffffu, a5, off);
    }
    int w = t >> 5, lane = t & 31;
    if (lane == 0) {
        sred[w][0] = a0; sred[w][1] = a1; sred[w][2] = a2;
        sred[w][3] = a3; sred[w][4] = a4; sred[w][5] = a5;
    }
    __syncthreads();

    if (t == 0) {
        float s0 = 0.f, s1 = 0.f, s2 = 0.f, s3 = 0.f, s4 = 0.f, s5 = 0.f;
        #pragma unroll
        for (int k = 0; k < 8; k++) {
            s0 += sred[k][0]; s1 += sred[k][1]; s2 += sred[k][2];
            s3 += sred[k][3]; s4 += sred[k][4]; s5 += sred[k][5];
        }
        float gi_r = s0 + bih[j];
        float gi_z = s1 + bih[H + j];
        float gi_n = s2 + bih[2 * H + j];
        float gh_r = s3 + bhh[j];
        float gh_z = s4 + bhh[H + j];
        float gh_n = s5 + bhh[2 * H + j];

        float r = 1.0f / (1.0f + expf(-(gi_r + gh_r)));
        float z = 1.0f / (1.0f + expf(-(gi_z + gh_z)));
        float n = tanhf(gi_n + r * gh_n);
        float h_old = ((const float*)sh)[j];   // careful: sh holds full h vector
        float h_new = (1.0f - z) * n + z * h_old;

        g_xbuf[layer + 1][j] = h_new;          // input for next stage
        d_out[V + layer * H + j] = h_new;      // hidden_new output
    }
}

// ---------------- kernel 3: output projection (the big one, 206 MB) ----------------
// 1 warp per vocab row, 8 warps per block. Lane-strided float4: 512B per ld per warp.
__global__ void __launch_bounds__(256) out_proj_kernel(
    const float* __restrict__ W,    // d_in[7], (V,H)
    const float* __restrict__ b)    // d_in[8], (V,)
{
    __shared__ float4 sx[H / 4];
    int t = threadIdx.x;
    sx[t] = ((const float4*)g_xbuf[2])[t];
    __syncthreads();

    int warp = t >> 5, lane = t & 31;
    int row = blockIdx.x * 8 + warp;
    if (row >= V) return;

    const float4* wr = (const float4*)(W + (size_t)row * H);
    float acc = 0.0f;
    #pragma unroll
    for (int k = 0; k < 8; k++) {
        int idx = lane + 32 * k;
        float4 w4 = wr[idx];
        float4 x4 = sx[idx];
        acc += w4.x * x4.x + w4.y * x4.y + w4.z * x4.z + w4.w * x4.w;
    }
    #pragma unroll
    for (int off = 16; off > 0; off >>= 1)
        acc += __shfl_down_sync(0xffffffffu, acc, off);
    if (lane == 0)
        g_logits[row] = acc + b[row];
}

// ---------------- kernel 4: log-sum-exp (single block, logits are L2-resident) ----------------
__global__ void __launch_bounds__(1024) lse_kernel() {
    __shared__ float sm[1024];
    int t = threadIdx.x;

    float m = -1e30f;
    for (int i = t; i < V; i += 1024) m = fmaxf(m, g_logits[i]);
    sm[t] = m;
    __syncthreads();
    #pragma unroll
    for (int s = 512; s > 0; s >>= 1) {
        if (t < s) sm[t] = fmaxf(sm[t], sm[t + s]);
        __syncthreads();
    }
    float mx = sm[0];
    __syncthreads();

    float su = 0.0f;
    for (int i = t; i < V; i += 1024) su += expf(g_logits[i] - mx);
    sm[t] = su;
    __syncthreads();
    #pragma unroll
    for (int s = 512; s > 0; s >>= 1) {
        if (t < s) sm[t] += sm[t + s];
        __syncthreads();
    }
    if (t == 0) g_lse = mx + logf(sm[0]);
}

// ---------------- kernel 5: write logprobs ----------------
__global__ void write_logprobs_kernel(float* __restrict__ d_out) {
    int i = blockIdx.x * blockDim.x + threadIdx.x;
    if (i < V) d_out[i] = g_logits[i] - g_lse;
}

// ---------------- launch ----------------
extern "C" void kernel_launch(void* const* d_in, const int* in_sizes, int n_in,
                              void* d_out, int out_size) {
    const long long* tok  = (const long long*)d_in[0];
    const float* hidden   = (const float*)d_in[1];
    const float* emb      = (const float*)d_in[2];
    const float* W_ih     = (const float*)d_in[3];
    const float* W_hh     = (const float*)d_in[4];
    const float* b_ih     = (const float*)d_in[5];
    const float* b_hh     = (const float*)d_in[6];
    const float* W_out    = (const float*)d_in[7];
    const float* b_out    = (const float*)d_in[8];
    float* out = (float*)d_out;

    embed_relu_kernel<<<H / 256, 256>>>(tok, emb);

    for (int l = 0; l < 2; l++) {
        gru_layer_kernel<<<H, 256>>>(
            l, hidden,
            W_ih + (size_t)l * 3 * H * H,
            W_hh + (size_t)l * 3 * H * H,
            b_ih + (size_t)l * 3 * H,
            b_hh + (size_t)l * 3 * H,
            out);
    }

    out_proj_kernel<<<(V + 7) / 8, 256>>>(W_out, b_out);
    lse_kernel<<<1, 1024>>>();
    write_logprobs_kernel<<<(V + 255) / 256, 256>>>(out);
}

// round 2
// speedup vs baseline: 1.2645x; 1.2645x over previous
#include <cuda_runtime.h>

#define H 1024
#define V 50257

// ---------------- scratch (no allocation allowed) ----------------
__device__ float g_gi0[3 * H];
__device__ float g_gh0[3 * H];
__device__ float g_gh1[3 * H];
__device__ float g_x1[H];     // h_new layer0 (input to layer1)
__device__ float g_x2[H];     // h_new layer1 (input to out_proj)
__device__ float g_sumexp;

__device__ __forceinline__ float dot4(float4 a, float4 b) {
    return a.x * b.x + a.y * b.y + a.z * b.z + a.w * b.w;
}

__device__ __forceinline__ float warp_sum(float a) {
    #pragma unroll
    for (int off = 16; off > 0; off >>= 1)
        a += __shfl_down_sync(0xffffffffu, a, off);
    return a;
}

// ============ K1: fused matvec x3 (36 MB) ============
// job 0: gi0 = W_ih[0] @ relu(emb[tok])
// job 1: gh0 = W_hh[0] @ hidden[0]
// job 2: gh1 = W_hh[1] @ hidden[1]
// warp-per-row, 8 warps/block, 384 blocks per job -> grid 1152.
__global__ void __launch_bounds__(256) mv3_kernel(
    const long long* __restrict__ tok,
    const float* __restrict__ hidden,
    const float* __restrict__ emb,
    const float* __restrict__ Wih,
    const float* __restrict__ Whh)
{
    __shared__ float4 sv[H / 4];
    int bid = blockIdx.x;
    int job = bid / 384;
    int t = threadIdx.x;

    const float* W;
    float* out;
    if (job == 0)      { W = Wih;                       out = g_gi0; }
    else if (job == 1) { W = Whh;                       out = g_gh0; }
    else               { W = Whh + (size_t)3 * H * H;   out = g_gh1; }

    if (job == 0) {
        long long tk = tok[0];
        float4 e = ((const float4*)(emb + tk * (long long)H))[t];
        e.x = fmaxf(e.x, 0.0f); e.y = fmaxf(e.y, 0.0f);
        e.z = fmaxf(e.z, 0.0f); e.w = fmaxf(e.w, 0.0f);
        sv[t] = e;
    } else {
        sv[t] = ((const float4*)(hidden + (job - 1) * H))[t];
    }
    __syncthreads();

    int warp = t >> 5, lane = t & 31;
    int r = (bid % 384) * 8 + warp;
    const float4* wr = (const float4*)(W + (size_t)r * H);

    float acc = 0.0f;
    #pragma unroll
    for (int k = 0; k < 8; k++) {
        int idx = lane + 32 * k;
        float4 w4 = __ldcs(&wr[idx]);
        acc += dot4(w4, sv[idx]);
    }
    acc = warp_sum(acc);
    if (lane == 0) out[r] = acc;
}

// ============ K2: gates layer 0 (tiny, L2-resident) ============
__global__ void __launch_bounds__(256) gates0_kernel(
    const float* __restrict__ hidden,
    const float* __restrict__ bih,
    const float* __restrict__ bhh,
    float* __restrict__ d_out)
{
    int j = blockIdx.x * 256 + threadIdx.x;
    if (j == 0) g_sumexp = 0.0f;          // reset accumulator for this replay

    float gi_r = g_gi0[j]         + bih[j];
    float gi_z = g_gi0[H + j]     + bih[H + j];
    float gi_n = g_gi0[2 * H + j] + bih[2 * H + j];
    float gh_r = g_gh0[j]         + bhh[j];
    float gh_z = g_gh0[H + j]     + bhh[H + j];
    float gh_n = g_gh0[2 * H + j] + bhh[2 * H + j];

    float r = 1.0f / (1.0f + expf(-(gi_r + gh_r)));
    float z = 1.0f / (1.0f + expf(-(gi_z + gh_z)));
    float n = tanhf(gi_n + r * gh_n);
    float h = hidden[j];
    float hn = (1.0f - z) * n + z * h;

    g_x1[j] = hn;
    d_out[V + j] = hn;
}

// ============ K3: layer-1 gi matvec (12 MB) fused with gates ============
// block j computes output element j: 3 rows of W_ih[1], gh1 precomputed.
__global__ void __launch_bounds__(256) gru1_kernel(
    const float* __restrict__ hidden,
    const float* __restrict__ Wih1,     // W_ih + 3H*H
    const float* __restrict__ bih1,     // b_ih + 3H
    const float* __restrict__ bhh1,     // b_hh + 3H
    float* __restrict__ d_out)
{
    __shared__ float4 sx[H / 4];
    __shared__ float sred[8][3];
    int t = threadIdx.x;
    sx[t] = ((const float4*)g_x1)[t];
    __syncthreads();

    int j = blockIdx.x;
    const float4* w0 = (const float4*)(Wih1 + (size_t)j * H);
    const float4* w1 = (const float4*)(Wih1 + (size_t)(H + j) * H);
    const float4* w2 = (const float4*)(Wih1 + (size_t)(2 * H + j) * H);

    float4 xv = sx[t];
    float a0 = dot4(__ldcs(&w0[t]), xv);
    float a1 = dot4(__ldcs(&w1[t]), xv);
    float a2 = dot4(__ldcs(&w2[t]), xv);

    a0 = warp_sum(a0); a1 = warp_sum(a1); a2 = warp_sum(a2);
    int w = t >> 5, lane = t & 31;
    if (lane == 0) { sred[w][0] = a0; sred[w][1] = a1; sred[w][2] = a2; }
    __syncthreads();

    if (t == 0) {
        float s0 = 0.f, s1 = 0.f, s2 = 0.f;
        #pragma unroll
        for (int k = 0; k < 8; k++) { s0 += sred[k][0]; s1 += sred[k][1]; s2 += sred[k][2]; }

        float gi_r = s0 + bih1[j];
        float gi_z = s1 + bih1[H + j];
        float gi_n = s2 + bih1[2 * H + j];
        float gh_r = g_gh1[j]         + bhh1[j];
        float gh_z = g_gh1[H + j]     + bhh1[H + j];
        float gh_n = g_gh1[2 * H + j] + bhh1[2 * H + j];

        float r = 1.0f / (1.0f + expf(-(gi_r + gh_r)));
        float z = 1.0f / (1.0f + expf(-(gi_z + gh_z)));
        float n = tanhf(gi_n + r * gh_n);
        float h = hidden[H + j];
        float hn = (1.0f - z) * n + z * h;

        g_x2[j] = hn;
        d_out[V + H + j] = hn;
    }
}

// ============ K4: output projection (206 MB) + sum-exp accumulation ============
// 2 rows per warp (16 LDG.128 in flight), 16 rows per block.
__global__ void __launch_bounds__(256) out_proj_kernel(
    const float* __restrict__ W,
    const float* __restrict__ b,
    float* __restrict__ d_out)
{
    __shared__ float4 sx[H / 4];
    __shared__ float sexp[16];
    int t = threadIdx.x;
    sx[t] = ((const float4*)g_x2)[t];
    __syncthreads();

    int warp = t >> 5, lane = t & 31;
    int row0 = blockIdx.x * 16 + warp * 2;
    bool v0 = row0 < V;
    bool v1 = row0 + 1 < V;
    size_t r0 = v0 ? (size_t)row0 : 0;
    size_t r1 = v1 ? (size_t)(row0 + 1) : 0;

    const float4* w0 = (const float4*)(W + r0 * H);
    const float4* w1 = (const float4*)(W + r1 * H);

    float acc0 = 0.0f, acc1 = 0.0f;
    #pragma unroll
    for (int k = 0; k < 8; k++) {
        int idx = lane + 32 * k;
        float4 x4 = sx[idx];
        float4 a4 = __ldcs(&w0[idx]);
        float4 b4 = __ldcs(&w1[idx]);
        acc0 += dot4(a4, x4);
        acc1 += dot4(b4, x4);
    }
    acc0 = warp_sum(acc0);
    acc1 = warp_sum(acc1);

    if (lane == 0) {
        float e0 = 0.0f, e1 = 0.0f;
        if (v0) { float lg = acc0 + b[r0]; d_out[r0] = lg; e0 = expf(lg); }
        if (v1) { float lg = acc1 + b[r1]; d_out[r1] = lg; e1 = expf(lg); }
        sexp[warp * 2]     = e0;
        sexp[warp * 2 + 1] = e1;
    }
    __syncthreads();
    if (t == 0) {
        float s = 0.0f;
        #pragma unroll
        for (int k = 0; k < 16; k++) s += sexp[k];
        atomicAdd(&g_sumexp, s);
    }
}

// ============ K5: finalize logprobs (in-place, L2-resident) ============
__global__ void finalize_kernel(float* __restrict__ d_out) {
    int i = blockIdx.x * blockDim.x + threadIdx.x;
    float lse = logf(g_sumexp);
    if (i < V) d_out[i] -= lse;
}

// ---------------- launch ----------------
extern "C" void kernel_launch(void* const* d_in, const int* in_sizes, int n_in,
                              void* d_out, int out_size) {
    const long long* tok  = (const long long*)d_in[0];
    const float* hidden   = (const float*)d_in[1];
    const float* emb      = (const float*)d_in[2];
    const float* W_ih     = (const float*)d_in[3];
    const float* W_hh     = (const float*)d_in[4];
    const float* b_ih     = (const float*)d_in[5];
    const float* b_hh     = (const float*)d_in[6];
    const float* W_out    = (const float*)d_in[7];
    const float* b_out    = (const float*)d_in[8];
    float* out = (float*)d_out;

    mv3_kernel<<<1152, 256>>>(tok, hidden, emb, W_ih, W_hh);
    gates0_kernel<<<4, 256>>>(hidden, b_ih, b_hh, out);
    gru1_kernel<<<H, 256>>>(hidden,
                            W_ih + (size_t)3 * H * H,
                            b_ih + 3 * H,
                            b_hh + 3 * H,
                            out);
    out_proj_kernel<<<(V + 15) / 16, 256>>>(W_out, b_out, out);
    finalize_kernel<<<(V + 255) / 256, 256>>>(out);
}